// round 1
// baseline (speedup 1.0000x reference)
#include <cuda_runtime.h>
#include <math.h>

// ---------------- problem constants ----------------
#define Bb   2
#define Cc   192
#define Hh   256
#define Ww   256
#define HW   65536           // 256*256
#define NPIX 131072          // B*H*W
#define DWIN 3072            // 16*C
#define NWIN 8192            // B*(H/4)*(W/4)
#define DH   768             // 4*C

// ---------------- scratch (device globals: allocation-free) ----------------
__device__ float g_wf[(size_t)DWIN * DWIN];        //  37.7 MB
__device__ float g_Xw[(size_t)NWIN * DWIN];        // 100.7 MB
__device__ float g_Y1[(size_t)NWIN * DWIN];        // 100.7 MB
__device__ float g_Z [(size_t)NPIX * Cc];          // 100.7 MB
__device__ float g_X2[(size_t)NPIX * Cc];          // 100.7 MB
__device__ float g_T [(size_t)NPIX * Cc];          // 100.7 MB
__device__ float g_U [(size_t)NPIX * DH];          // 402.7 MB

// ---------------- helpers ----------------
__device__ __forceinline__ float gelu_exact(float x) {
    return 0.5f * x * (1.0f + erff(x * 0.70710678118654752f));
}

// sign of e_i * e_j in the 16-dim Cayley-Dickson (sedenion) algebra.
// product index is always i XOR j.
__device__ __forceinline__ int cd_sign16(int i, int j) {
    int s = 1;
    for (int n = 16; n > 1;) {
        int h = n >> 1;
        if (i < h && j < h) {
            // sign_h(i, j)
        } else if (i < h) {            // j >= h : c2 = b2*a1 -> sign_h(j-h, i)
            int t = j - h; j = i; i = t;
        } else if (j < h) {            // i >= h : a2*conj(b1) -> cs(j)*sign_h(i-h, j)
            if (j != 0) s = -s;
            i = i - h;
        } else {                       // both >= h : -conj(b2)*a2 -> -cs(jp)*sign_h(jp, ip)
            int ip = i - h, jp = j - h;
            if (jp == 0) s = -s;       // -cs = -1 when jp==0, +1 otherwise
            i = jp; j = ip;
        }
        n = h;
    }
    return s;
}

// ---------------- kernel: build wf (3072 x 3072) ----------------
// wf[i*C+a][k*C+b] = sign16(i, i^k) * w_sed[i^k][a][b]
__global__ void build_wf_kernel(const float* __restrict__ w_sed, float* __restrict__ wf) {
    int e4 = blockIdx.x * blockDim.x + threadIdx.x;   // one float4 per thread
    if (e4 >= DWIN * (DWIN / 4)) return;
    int row  = e4 / (DWIN / 4);
    int col4 = (e4 % (DWIN / 4)) * 4;
    int i = row / Cc, a = row % Cc;
    int k = col4 / Cc, b = col4 % Cc;
    int j = i ^ k;
    int s = cd_sign16(i, j);
    float4 v = *(const float4*)(w_sed + ((size_t)j * Cc + a) * Cc + b);
    if (s < 0) { v.x = -v.x; v.y = -v.y; v.z = -v.z; v.w = -v.w; }
    *(float4*)(wf + (size_t)row * DWIN + col4) = v;
}

// ---------------- kernel: LN1 over channels + window scatter ----------------
__global__ void ln1_window_kernel(const float* __restrict__ x,
                                  const float* __restrict__ g,
                                  const float* __restrict__ be,
                                  float* __restrict__ Xw) {
    int n = blockIdx.x * blockDim.x + threadIdx.x;    // pixel id (b,h,w)
    if (n >= NPIX) return;
    int b = n >> 16, hw = n & (HW - 1);
    int h = hw >> 8, w = hw & 255;
    const float* px = x + (size_t)b * Cc * HW + hw;
    float s = 0.f, s2 = 0.f;
#pragma unroll 4
    for (int c = 0; c < Cc; c++) {
        float v = px[(size_t)c * HW];
        s += v; s2 += v * v;
    }
    float m  = s * (1.0f / Cc);
    float rs = rsqrtf(s2 * (1.0f / Cc) - m * m + 1e-5f);
    int r = (b << 12) + ((h >> 2) << 6) + (w >> 2);   // window row
    int p = ((h & 3) << 2) + (w & 3);                 // position in window
    float* dst = Xw + (size_t)r * DWIN + p * Cc;
#pragma unroll 4
    for (int c = 0; c < Cc; c++) {
        float v = px[(size_t)c * HW];
        dst[c] = (v - m) * rs * g[c] + be[c];
    }
}

// ---------------- kernel: gather windows back + GELU ----------------
__global__ void gather_gelu_kernel(const float* __restrict__ Y1, float* __restrict__ Z) {
    int e4 = blockIdx.x * blockDim.x + threadIdx.x;
    if (e4 >= NPIX * (Cc / 4)) return;
    int n  = e4 / (Cc / 4);
    int c4 = (e4 % (Cc / 4)) * 4;
    int b = n >> 16, hw = n & (HW - 1);
    int h = hw >> 8, w = hw & 255;
    int r = (b << 12) + ((h >> 2) << 6) + (w >> 2);
    int p = ((h & 3) << 2) + (w & 3);
    float4 v = *(const float4*)(Y1 + (size_t)r * DWIN + p * Cc + c4);
    float4 o;
    o.x = gelu_exact(v.x); o.y = gelu_exact(v.y);
    o.z = gelu_exact(v.z); o.w = gelu_exact(v.w);
    *(float4*)(Z + (size_t)n * Cc + c4) = o;
}

// ---------------- kernel: LN2 (row-major 131072 x 192), one warp per row ----
__global__ void ln2_kernel(const float* __restrict__ X2,
                           const float* __restrict__ g,
                           const float* __restrict__ be,
                           float* __restrict__ T) {
    int gt   = blockIdx.x * blockDim.x + threadIdx.x;
    int row  = gt >> 5;
    int lane = gt & 31;
    if (row >= NPIX) return;
    const float* src = X2 + (size_t)row * Cc;
    float vals[6];
    float s = 0.f, s2 = 0.f;
#pragma unroll
    for (int i = 0; i < 6; i++) {
        float v = src[lane + i * 32];
        vals[i] = v; s += v; s2 += v * v;
    }
#pragma unroll
    for (int o = 16; o > 0; o >>= 1) {
        s  += __shfl_xor_sync(0xffffffffu, s,  o);
        s2 += __shfl_xor_sync(0xffffffffu, s2, o);
    }
    float m  = s * (1.0f / Cc);
    float rs = rsqrtf(s2 * (1.0f / Cc) - m * m + 1e-5f);
    float* dst = T + (size_t)row * Cc;
#pragma unroll
    for (int i = 0; i < 6; i++) {
        int c = lane + i * 32;
        dst[c] = (vals[i] - m) * rs * g[c] + be[c];
    }
}

// ---------------- tiled SGEMM with fused epilogues ----------------
// MODE 0: C = A@B                               (sedenion GEMM)
// MODE 1: C = A@B + bias + x_bchw (residual)    (proj, writes X2 row-major)
// MODE 2: C = gelu(A@B + bias)                  (fc1)
// MODE 3: out_bchw = res_rowmajor + A@B + bias  (fc2, transposed store)
#define BM 128
#define BN 128
#define BK 16
#define TM 8
#define TN 8

template <int MODE>
__global__ __launch_bounds__(256)
void gemm_kernel(const float* __restrict__ A, const float* __restrict__ B,
                 float* __restrict__ C, int M, int N, int K,
                 const float* __restrict__ bias,
                 const float* __restrict__ res) {
    __shared__ float As[BK][BM + 1];
    __shared__ float Bs[BK][BN];

    int tid  = threadIdx.x;
    int row0 = blockIdx.y * BM;
    int col0 = blockIdx.x * BN;
    int tr = (tid >> 4) * TM;   // 0..120
    int tc = (tid & 15) * TN;   // 0..120

    float acc[TM][TN];
#pragma unroll
    for (int i = 0; i < TM; i++)
#pragma unroll
        for (int j = 0; j < TN; j++) acc[i][j] = 0.f;

    for (int kt = 0; kt < K; kt += BK) {
        // load A tile (BM x BK), stored transposed into As[k][m]
#pragma unroll
        for (int l = 0; l < 2; l++) {
            int idx = (tid + l * 256) * 4;
            int ar = idx / BK;
            int ak = idx % BK;
            float4 v = *(const float4*)(A + (size_t)(row0 + ar) * K + kt + ak);
            As[ak + 0][ar] = v.x; As[ak + 1][ar] = v.y;
            As[ak + 2][ar] = v.z; As[ak + 3][ar] = v.w;
        }
        // load B tile (BK x BN), N-guarded
#pragma unroll
        for (int l = 0; l < 2; l++) {
            int idx = (tid + l * 256) * 4;
            int bk  = idx / BN;
            int bn  = idx % BN;
            float4 v;
            if (col0 + bn < N)
                v = *(const float4*)(B + (size_t)(kt + bk) * N + col0 + bn);
            else
                v = make_float4(0.f, 0.f, 0.f, 0.f);
            *(float4*)&Bs[bk][bn] = v;
        }
        __syncthreads();
#pragma unroll
        for (int k = 0; k < BK; k++) {
            float ra[TM], rb[TN];
#pragma unroll
            for (int i = 0; i < TM; i++) ra[i] = As[k][tr + i];
#pragma unroll
            for (int j = 0; j < TN; j++) rb[j] = Bs[k][tc + j];
#pragma unroll
            for (int i = 0; i < TM; i++)
#pragma unroll
                for (int j = 0; j < TN; j++)
                    acc[i][j] = fmaf(ra[i], rb[j], acc[i][j]);
        }
        __syncthreads();
    }

    // epilogue
#pragma unroll
    for (int i = 0; i < TM; i++) {
        int r = row0 + tr + i;
#pragma unroll
        for (int j = 0; j < TN; j++) {
            int c = col0 + tc + j;
            if (c >= N) continue;
            float v = acc[i][j];
            if (MODE == 0) {
                C[(size_t)r * N + c] = v;
            } else if (MODE == 1) {
                int b = r >> 16, hw = r & (HW - 1);
                float xr = res[(size_t)b * Cc * HW + (size_t)c * HW + hw];
                C[(size_t)r * N + c] = v + bias[c] + xr;
            } else if (MODE == 2) {
                C[(size_t)r * N + c] = gelu_exact(v + bias[c]);
            } else {  // MODE 3: transposed store to BCHW + residual (row-major res)
                int b = r >> 16, hw = r & (HW - 1);
                float x2 = res[(size_t)r * Cc + c];
                C[(size_t)b * Cc * HW + (size_t)c * HW + hw] = x2 + v + bias[c];
            }
        }
    }
}

// ---------------- launch ----------------
extern "C" void kernel_launch(void* const* d_in, const int* in_sizes, int n_in,
                              void* d_out, int out_size) {
    const float* x       = (const float*)d_in[0];
    const float* norm1_g = (const float*)d_in[1];
    const float* norm1_b = (const float*)d_in[2];
    const float* w_sed   = (const float*)d_in[3];
    const float* proj_w  = (const float*)d_in[4];
    const float* proj_b  = (const float*)d_in[5];
    const float* norm2_g = (const float*)d_in[6];
    const float* norm2_b = (const float*)d_in[7];
    const float* fc1_w   = (const float*)d_in[8];
    const float* fc1_b   = (const float*)d_in[9];
    const float* fc2_w   = (const float*)d_in[10];
    const float* fc2_b   = (const float*)d_in[11];
    float* out = (float*)d_out;

    float *wf, *Xw, *Y1, *Z, *X2, *T, *U;
    cudaGetSymbolAddress((void**)&wf, g_wf);
    cudaGetSymbolAddress((void**)&Xw, g_Xw);
    cudaGetSymbolAddress((void**)&Y1, g_Y1);
    cudaGetSymbolAddress((void**)&Z,  g_Z);
    cudaGetSymbolAddress((void**)&X2, g_X2);
    cudaGetSymbolAddress((void**)&T,  g_T);
    cudaGetSymbolAddress((void**)&U,  g_U);

    // 1. wf from w_sed (sedenion structure)
    build_wf_kernel<<<(DWIN * (DWIN / 4) + 255) / 256, 256>>>(w_sed, wf);

    // 2. LN1 + window partition
    ln1_window_kernel<<<(NPIX + 255) / 256, 256>>>(x, norm1_g, norm1_b, Xw);

    // 3. Sedenion GEMM: Y1 = Xw @ wf   (8192 x 3072 x 3072)
    gemm_kernel<0><<<dim3(DWIN / BN, NWIN / BM), 256>>>(Xw, wf, Y1,
                                                        NWIN, DWIN, DWIN,
                                                        nullptr, nullptr);

    // 4. reverse window + GELU -> Z (131072 x 192)
    gather_gelu_kernel<<<(NPIX * (Cc / 4) + 255) / 256, 256>>>(Y1, Z);

    // 5. proj + bias + residual(x) -> X2 (131072 x 192)
    gemm_kernel<1><<<dim3((Cc + BN - 1) / BN, NPIX / BM), 256>>>(Z, proj_w, X2,
                                                                 NPIX, Cc, Cc,
                                                                 proj_b, x);

    // 6. LN2 -> T
    ln2_kernel<<<(NPIX * 32 + 255) / 256, 256>>>(X2, norm2_g, norm2_b, T);

    // 7. fc1 + bias + GELU -> U (131072 x 768)
    gemm_kernel<2><<<dim3(DH / BN, NPIX / BM), 256>>>(T, fc1_w, U,
                                                      NPIX, DH, Cc,
                                                      fc1_b, nullptr);

    // 8. fc2 + bias + residual(X2), transposed store -> out (B,C,H,W)
    gemm_kernel<3><<<dim3((Cc + BN - 1) / BN, NPIX / BM), 256>>>(U, fc2_w, out,
                                                                 NPIX, Cc, DH,
                                                                 fc2_b, X2);
}

// round 3
// speedup vs baseline: 2.2288x; 2.2288x over previous
#include <cuda_runtime.h>
#include <cstdint>
#include <math.h>

// ---------------- problem constants ----------------
#define Cc   192
#define HW   65536           // 256*256
#define NPIX 131072          // B*H*W
#define DWIN 3072            // 16*C
#define NWIN 8192            // B*(H/4)*(W/4)
#define DH   768             // 4*C

// ---------------- scratch (device globals: allocation-free) ----------------
__device__ float g_wf[(size_t)DWIN * DWIN];        //  37.7 MB  ([K][N] row-major)
__device__ float g_Xw[(size_t)NWIN * DWIN];        // 100.7 MB
__device__ float g_Y1[(size_t)NWIN * DWIN];        // 100.7 MB
__device__ float g_Z [(size_t)NPIX * Cc];          // 100.7 MB
__device__ float g_X2[(size_t)NPIX * Cc];          // 100.7 MB
__device__ float g_T [(size_t)NPIX * Cc];          // 100.7 MB
__device__ float g_U [(size_t)NPIX * DH];          // 402.7 MB

// ---------------- helpers ----------------
__device__ __forceinline__ float gelu_exact(float x) {
    return 0.5f * x * (1.0f + erff(x * 0.70710678118654752f));
}
__device__ __forceinline__ float to_tf32(float x) {
    uint32_t r;
    asm("cvt.rna.tf32.f32 %0, %1;" : "=r"(r) : "f"(x));
    return __uint_as_float(r);
}

__device__ __forceinline__ int cd_sign16(int i, int j) {
    int s = 1;
    for (int n = 16; n > 1;) {
        int h = n >> 1;
        if (i < h && j < h) {
        } else if (i < h) {
            int t = j - h; j = i; i = t;
        } else if (j < h) {
            if (j != 0) s = -s;
            i = i - h;
        } else {
            int ip = i - h, jp = j - h;
            if (jp == 0) s = -s;
            i = jp; j = ip;
        }
        n = h;
    }
    return s;
}

// ---------------- kernel: build wf (3072 x 3072, [K][N]) ----------------
// wf[i*C+a][k*C+b] = sign16(i, i^k) * w_sed[i^k][a][b]
__global__ void build_wf_kernel(const float* __restrict__ w_sed, float* __restrict__ wf) {
    int e4 = blockIdx.x * blockDim.x + threadIdx.x;
    if (e4 >= DWIN * (DWIN / 4)) return;
    int row  = e4 / (DWIN / 4);
    int col4 = (e4 % (DWIN / 4)) * 4;
    int i = row / Cc, a = row % Cc;
    int k = col4 / Cc, b = col4 % Cc;
    int j = i ^ k;
    int s = cd_sign16(i, j);
    float4 v = *(const float4*)(w_sed + ((size_t)j * Cc + a) * Cc + b);
    if (s < 0) { v.x = -v.x; v.y = -v.y; v.z = -v.z; v.w = -v.w; }
    *(float4*)(wf + (size_t)row * DWIN + col4) = v;
}

// ---------------- kernel: LN1 over channels + window scatter ----------------
__global__ void ln1_window_kernel(const float* __restrict__ x,
                                  const float* __restrict__ g,
                                  const float* __restrict__ be,
                                  float* __restrict__ Xw) {
    int n = blockIdx.x * blockDim.x + threadIdx.x;
    if (n >= NPIX) return;
    int b = n >> 16, hw = n & (HW - 1);
    int h = hw >> 8, w = hw & 255;
    const float* px = x + (size_t)b * Cc * HW + hw;
    float s = 0.f, s2 = 0.f;
#pragma unroll 4
    for (int c = 0; c < Cc; c++) {
        float v = px[(size_t)c * HW];
        s += v; s2 += v * v;
    }
    float m  = s * (1.0f / Cc);
    float rs = rsqrtf(s2 * (1.0f / Cc) - m * m + 1e-5f);
    int r = (b << 12) + ((h >> 2) << 6) + (w >> 2);
    int p = ((h & 3) << 2) + (w & 3);
    float* dst = Xw + (size_t)r * DWIN + p * Cc;
#pragma unroll 4
    for (int c = 0; c < Cc; c++) {
        float v = px[(size_t)c * HW];
        dst[c] = (v - m) * rs * g[c] + be[c];
    }
}

// ---------------- kernel: gather windows back + GELU ----------------------
__global__ void gather_gelu_kernel(const float* __restrict__ Y1, float* __restrict__ Z) {
    int e4 = blockIdx.x * blockDim.x + threadIdx.x;
    if (e4 >= NPIX * (Cc / 4)) return;
    int n  = e4 / (Cc / 4);
    int c4 = (e4 % (Cc / 4)) * 4;
    int b = n >> 16, hw = n & (HW - 1);
    int h = hw >> 8, w = hw & 255;
    int r = (b << 12) + ((h >> 2) << 6) + (w >> 2);
    int p = ((h & 3) << 2) + (w & 3);
    float4 v = *(const float4*)(Y1 + (size_t)r * DWIN + p * Cc + c4);
    float4 o;
    o.x = gelu_exact(v.x); o.y = gelu_exact(v.y);
    o.z = gelu_exact(v.z); o.w = gelu_exact(v.w);
    *(float4*)(Z + (size_t)n * Cc + c4) = o;
}

// ---------------- kernel: LN2, one warp per row ---------------------------
__global__ void ln2_kernel(const float* __restrict__ X2,
                           const float* __restrict__ g,
                           const float* __restrict__ be,
                           float* __restrict__ T) {
    int gt   = blockIdx.x * blockDim.x + threadIdx.x;
    int row  = gt >> 5;
    int lane = gt & 31;
    if (row >= NPIX) return;
    const float* src = X2 + (size_t)row * Cc;
    float vals[6];
    float s = 0.f, s2 = 0.f;
#pragma unroll
    for (int i = 0; i < 6; i++) {
        float v = src[lane + i * 32];
        vals[i] = v; s += v; s2 += v * v;
    }
#pragma unroll
    for (int o = 16; o > 0; o >>= 1) {
        s  += __shfl_xor_sync(0xffffffffu, s,  o);
        s2 += __shfl_xor_sync(0xffffffffu, s2, o);
    }
    float m  = s * (1.0f / Cc);
    float rs = rsqrtf(s2 * (1.0f / Cc) - m * m + 1e-5f);
    float* dst = T + (size_t)row * Cc;
#pragma unroll
    for (int i = 0; i < 6; i++) {
        int c = lane + i * 32;
        dst[c] = (vals[i] - m) * rs * g[c] + be[c];
    }
}

// ---------------- tf32 mma.sync GEMM ----------------------------------------
// D[M,N] = A[M,K] @ B[K,N]   (both row-major; inputs rounded to tf32)
// CTA tile 128x128x32, 8 warps (4x2), warp tile 32x64, mma m16n8k8.
// MODE 0: C = D
// MODE 1: C = D + bias + res_bchw       (proj + residual, row-major out)
// MODE 2: C = gelu(D + bias)            (fc1)
// MODE 3: out_bchw = res_rowmaj + D + b (fc2, transposed store)
#define SSTR 136   // smem row stride (floats): (8k+m)%32 conflict-free frag loads

__device__ __forceinline__ void mma_tf32(float* c, const uint32_t* a, const uint32_t* b) {
    asm volatile(
        "mma.sync.aligned.m16n8k8.row.col.f32.tf32.tf32.f32 "
        "{%0,%1,%2,%3}, {%4,%5,%6,%7}, {%8,%9}, {%0,%1,%2,%3};"
        : "+f"(c[0]), "+f"(c[1]), "+f"(c[2]), "+f"(c[3])
        : "r"(a[0]), "r"(a[1]), "r"(a[2]), "r"(a[3]), "r"(b[0]), "r"(b[1]));
}

template <int MODE>
__global__ __launch_bounds__(256)
void mma_gemm(const float* __restrict__ A, const float* __restrict__ Bm,
              float* __restrict__ C, int M, int N, int K,
              const float* __restrict__ bias, const float* __restrict__ res) {
    __shared__ float As[32 * SSTR];   // As[k][m], 128 m per row
    __shared__ float Bs[32 * SSTR];   // Bs[k][n], 128 n per row

    int tid  = threadIdx.x;
    int wid  = tid >> 5, lane = tid & 31;
    int wm   = wid & 3;               // 0..3 -> 32-row slice
    int wn   = wid >> 2;              // 0..1 -> 64-col slice
    int row0 = blockIdx.y * 128;
    int col0 = blockIdx.x * 128;
    int lg   = lane >> 2;             // group id 0..7
    int lt   = lane & 3;              // thread-in-group 0..3

    float cacc[2][8][4];
#pragma unroll
    for (int mt = 0; mt < 2; mt++)
#pragma unroll
        for (int nt = 0; nt < 8; nt++)
#pragma unroll
            for (int q = 0; q < 4; q++) cacc[mt][nt][q] = 0.f;

    int nk = K >> 5;
    for (int kt = 0; kt < nk; kt++) {
        // --- copy A tile: 128 rows x 32 k.  idx -> (r = idx&127, kc = (idx>>7)*4)
        // store lanes walk m (conflict-free); L1 sectors reused across warps.
#pragma unroll
        for (int i = 0; i < 4; i++) {
            int idx = tid + i * 256;
            int r   = idx & 127;
            int kc  = (idx >> 7) << 2;
            float4 v = *(const float4*)(A + (size_t)(row0 + r) * K + (kt << 5) + kc);
            As[(kc + 0) * SSTR + r] = to_tf32(v.x);
            As[(kc + 1) * SSTR + r] = to_tf32(v.y);
            As[(kc + 2) * SSTR + r] = to_tf32(v.z);
            As[(kc + 3) * SSTR + r] = to_tf32(v.w);
        }
        // --- copy B tile: 32 k x 128 n, straight (n contiguous), N-guarded
#pragma unroll
        for (int i = 0; i < 4; i++) {
            int idx = tid + i * 256;
            int k   = idx >> 5;
            int n4  = (idx & 31) << 2;
            float4 v;
            if (col0 + n4 < N)
                v = *(const float4*)(Bm + (size_t)((kt << 5) + k) * N + col0 + n4);
            else
                v = make_float4(0.f, 0.f, 0.f, 0.f);
            float* d = &Bs[k * SSTR + n4];
            d[0] = to_tf32(v.x); d[1] = to_tf32(v.y);
            d[2] = to_tf32(v.z); d[3] = to_tf32(v.w);
        }
        __syncthreads();

#pragma unroll
        for (int ks = 0; ks < 4; ks++) {
            int k0 = (ks << 3) + lt;
            uint32_t af[2][4], bf[8][2];
            const float* ab = &As[k0 * SSTR + wm * 32 + lg];
#pragma unroll
            for (int mt = 0; mt < 2; mt++) {
                const float* p = ab + mt * 16;
                af[mt][0] = __float_as_uint(p[0]);
                af[mt][1] = __float_as_uint(p[8]);
                af[mt][2] = __float_as_uint(p[4 * SSTR]);
                af[mt][3] = __float_as_uint(p[4 * SSTR + 8]);
            }
            const float* bb = &Bs[k0 * SSTR + wn * 64 + lg];
#pragma unroll
            for (int nt = 0; nt < 8; nt++) {
                const float* q = bb + nt * 8;
                bf[nt][0] = __float_as_uint(q[0]);
                bf[nt][1] = __float_as_uint(q[4 * SSTR]);
            }
#pragma unroll
            for (int mt = 0; mt < 2; mt++)
#pragma unroll
                for (int nt = 0; nt < 8; nt++)
                    mma_tf32(cacc[mt][nt], af[mt], bf[nt]);
        }
        __syncthreads();
    }

    // ---------------- epilogue ----------------
#pragma unroll
    for (int mt = 0; mt < 2; mt++) {
#pragma unroll
        for (int nt = 0; nt < 8; nt++) {
            int r = row0 + wm * 32 + mt * 16 + lg;
            int c = col0 + wn * 64 + nt * 8 + lt * 2;
            if (c >= N) continue;
#pragma unroll
            for (int half = 0; half < 2; half++) {
                int rr = r + half * 8;
                float v0 = cacc[mt][nt][half * 2 + 0];
                float v1 = cacc[mt][nt][half * 2 + 1];
                int rb = rr >> 16, rhw = rr & (HW - 1);
                if (MODE == 0) {
                    *(float2*)(C + (size_t)rr * N + c) = make_float2(v0, v1);
                } else if (MODE == 1) {
                    const float* rp = res + (size_t)rb * Cc * HW + rhw;
                    float o0 = v0 + bias[c]     + rp[(size_t)c * HW];
                    float o1 = v1 + bias[c + 1] + rp[(size_t)(c + 1) * HW];
                    *(float2*)(C + (size_t)rr * N + c) = make_float2(o0, o1);
                } else if (MODE == 2) {
                    *(float2*)(C + (size_t)rr * N + c) =
                        make_float2(gelu_exact(v0 + bias[c]), gelu_exact(v1 + bias[c + 1]));
                } else {
                    const float* rp = res + (size_t)rr * Cc;
                    float* op = C + (size_t)rb * Cc * HW + rhw;
                    op[(size_t)c * HW]       = rp[c]     + v0 + bias[c];
                    op[(size_t)(c + 1) * HW] = rp[c + 1] + v1 + bias[c + 1];
                }
            }
        }
    }
}

// ---------------- launch ----------------
extern "C" void kernel_launch(void* const* d_in, const int* in_sizes, int n_in,
                              void* d_out, int out_size) {
    const float* x       = (const float*)d_in[0];
    const float* norm1_g = (const float*)d_in[1];
    const float* norm1_b = (const float*)d_in[2];
    const float* w_sed   = (const float*)d_in[3];
    const float* proj_w  = (const float*)d_in[4];
    const float* proj_b  = (const float*)d_in[5];
    const float* norm2_g = (const float*)d_in[6];
    const float* norm2_b = (const float*)d_in[7];
    const float* fc1_w   = (const float*)d_in[8];
    const float* fc1_b   = (const float*)d_in[9];
    const float* fc2_w   = (const float*)d_in[10];
    const float* fc2_b   = (const float*)d_in[11];
    float* out = (float*)d_out;

    float *wf, *Xw, *Y1, *Z, *X2, *T, *U;
    cudaGetSymbolAddress((void**)&wf, g_wf);
    cudaGetSymbolAddress((void**)&Xw, g_Xw);
    cudaGetSymbolAddress((void**)&Y1, g_Y1);
    cudaGetSymbolAddress((void**)&Z,  g_Z);
    cudaGetSymbolAddress((void**)&X2, g_X2);
    cudaGetSymbolAddress((void**)&T,  g_T);
    cudaGetSymbolAddress((void**)&U,  g_U);

    // 0. wf from w_sed (sedenion structure), [K][N]
    build_wf_kernel<<<(DWIN * (DWIN / 4) + 255) / 256, 256>>>(w_sed, wf);

    // 1. LN1 + window partition
    ln1_window_kernel<<<(NPIX + 255) / 256, 256>>>(x, norm1_g, norm1_b, Xw);

    // 2. Sedenion GEMM: Y1 = Xw @ wf   (8192 x 3072 x 3072)
    mma_gemm<0><<<dim3(DWIN / 128, NWIN / 128), 256>>>(
        Xw, wf, Y1, NWIN, DWIN, DWIN, nullptr, nullptr);

    // 3. reverse window + GELU -> Z
    gather_gelu_kernel<<<(NPIX * (Cc / 4) + 255) / 256, 256>>>(Y1, Z);

    // 4. proj + bias + residual(x) -> X2   (131072 x 192 x 192)
    mma_gemm<1><<<dim3(2, NPIX / 128), 256>>>(
        Z, proj_w, X2, NPIX, Cc, Cc, proj_b, x);

    // 5. LN2 -> T
    ln2_kernel<<<(NPIX * 32 + 255) / 256, 256>>>(X2, norm2_g, norm2_b, T);

    // 6. fc1 + bias + GELU -> U   (131072 x 768 x 192)
    mma_gemm<2><<<dim3(DH / 128, NPIX / 128), 256>>>(
        T, fc1_w, U, NPIX, DH, Cc, fc1_b, nullptr);

    // 7. fc2 + bias + residual(X2), transposed store -> out  (131072 x 192 x 768)
    mma_gemm<3><<<dim3(2, NPIX / 128), 256>>>(
        U, fc2_w, out, NPIX, Cc, DH, fc2_b, X2);
}

// round 4
// speedup vs baseline: 4.4432x; 1.9935x over previous
#include <cuda_runtime.h>
#include <cuda_fp16.h>
#include <cstdint>
#include <math.h>

// ---------------- problem constants ----------------
#define Cc   192
#define HW   65536           // 256*256
#define NPIX 131072          // B*H*W
#define DWIN 3072            // 16*C
#define NWIN 8192            // B*(H/4)*(W/4)
#define DH   768             // 4*C

// ---------------- scratch (device globals: allocation-free) ----------------
__device__ __half g_wf [(size_t)DWIN * DWIN];      // 18.9 MB  ([K][N] row-major)
__device__ __half g_Xw [(size_t)NWIN * DWIN];      // 50.3 MB
__device__ __half g_Y1 [(size_t)NWIN * DWIN];      // 50.3 MB
__device__ __half g_Z  [(size_t)NPIX * Cc];        // 50.3 MB
__device__ float  g_X2 [(size_t)NPIX * Cc];        // 100.7 MB (residual chain: fp32)
__device__ __half g_T  [(size_t)NPIX * Cc];        // 50.3 MB
__device__ __half g_U  [(size_t)NPIX * DH];        // 201.3 MB
__device__ __half g_projH[Cc * Cc];
__device__ __half g_fc1H [Cc * DH];
__device__ __half g_fc2H [DH * Cc];

// ---------------- helpers ----------------
__device__ __forceinline__ float gelu_exact(float x) {
    return 0.5f * x * (1.0f + erff(x * 0.70710678118654752f));
}
__device__ __forceinline__ uint32_t smem_u32(const void* p) {
    uint32_t a;
    asm("{ .reg .u64 t; cvta.to.shared.u64 t, %1; cvt.u32.u64 %0, t; }" : "=r"(a) : "l"(p));
    return a;
}

__device__ __forceinline__ int cd_sign16(int i, int j) {
    int s = 1;
    for (int n = 16; n > 1;) {
        int h = n >> 1;
        if (i < h && j < h) {
        } else if (i < h) {
            int t = j - h; j = i; i = t;
        } else if (j < h) {
            if (j != 0) s = -s;
            i = i - h;
        } else {
            int ip = i - h, jp = j - h;
            if (jp == 0) s = -s;
            i = jp; j = ip;
        }
        n = h;
    }
    return s;
}

// ---------------- kernel: build wf (3072 x 3072, [K][N], fp16) -------------
__global__ void build_wf_kernel(const float* __restrict__ w_sed, __half* __restrict__ wf) {
    int e4 = blockIdx.x * blockDim.x + threadIdx.x;
    if (e4 >= DWIN * (DWIN / 4)) return;
    int row  = e4 / (DWIN / 4);
    int col4 = (e4 % (DWIN / 4)) * 4;
    int i = row / Cc, a = row % Cc;
    int k = col4 / Cc, b = col4 % Cc;
    int j = i ^ k;
    float s = (float)cd_sign16(i, j);
    float4 v = *(const float4*)(w_sed + ((size_t)j * Cc + a) * Cc + b);
    __half2* d = (__half2*)(wf + (size_t)row * DWIN + col4);
    d[0] = __floats2half2_rn(s * v.x, s * v.y);
    d[1] = __floats2half2_rn(s * v.z, s * v.w);
}

// ---------------- kernel: fp32 -> fp16 weight convert ----------------------
__global__ void convert_h_kernel(const float* __restrict__ w, __half* __restrict__ wh, int n) {
    int o = blockIdx.x * blockDim.x + threadIdx.x;
    if (o < n) wh[o] = __float2half_rn(w[o]);
}

// ---------------- kernel: LN1 over channels + window scatter (fp16 out) ----
__global__ void ln1_window_kernel(const float* __restrict__ x,
                                  const float* __restrict__ g,
                                  const float* __restrict__ be,
                                  __half* __restrict__ Xw) {
    int n = blockIdx.x * blockDim.x + threadIdx.x;
    if (n >= NPIX) return;
    int b = n >> 16, hw = n & (HW - 1);
    int h = hw >> 8, w = hw & 255;
    const float* px = x + (size_t)b * Cc * HW + hw;
    float s = 0.f, s2 = 0.f;
#pragma unroll 4
    for (int c = 0; c < Cc; c++) {
        float v = px[(size_t)c * HW];
        s += v; s2 += v * v;
    }
    float m  = s * (1.0f / Cc);
    float rs = rsqrtf(s2 * (1.0f / Cc) - m * m + 1e-5f);
    int r = (b << 12) + ((h >> 2) << 6) + (w >> 2);
    int p = ((h & 3) << 2) + (w & 3);
    __half* dst = Xw + (size_t)r * DWIN + p * Cc;
#pragma unroll 4
    for (int c = 0; c < Cc; c++) {
        float v = px[(size_t)c * HW];
        dst[c] = __float2half_rn((v - m) * rs * g[c] + be[c]);
    }
}

// ---------------- kernel: gather windows back + GELU (fp16 in/out) ---------
__global__ void gather_gelu_kernel(const __half* __restrict__ Y1, __half* __restrict__ Z) {
    int e4 = blockIdx.x * blockDim.x + threadIdx.x;
    if (e4 >= NPIX * (Cc / 4)) return;
    int n  = e4 / (Cc / 4);
    int c4 = (e4 % (Cc / 4)) * 4;
    int b = n >> 16, hw = n & (HW - 1);
    int h = hw >> 8, w = hw & 255;
    int r = (b << 12) + ((h >> 2) << 6) + (w >> 2);
    int p = ((h & 3) << 2) + (w & 3);
    const __half2* s = (const __half2*)(Y1 + (size_t)r * DWIN + p * Cc + c4);
    __half2 v0 = s[0], v1 = s[1];
    float2 f0 = __half22float2(v0), f1 = __half22float2(v1);
    __half2* d = (__half2*)(Z + (size_t)n * Cc + c4);
    d[0] = __floats2half2_rn(gelu_exact(f0.x), gelu_exact(f0.y));
    d[1] = __floats2half2_rn(gelu_exact(f1.x), gelu_exact(f1.y));
}

// ---------------- kernel: LN2, one warp per row (fp32 in, fp16 out) --------
__global__ void ln2_kernel(const float* __restrict__ X2,
                           const float* __restrict__ g,
                           const float* __restrict__ be,
                           __half* __restrict__ T) {
    int gt   = blockIdx.x * blockDim.x + threadIdx.x;
    int row  = gt >> 5;
    int lane = gt & 31;
    if (row >= NPIX) return;
    const float* src = X2 + (size_t)row * Cc;
    float vals[6];
    float s = 0.f, s2 = 0.f;
#pragma unroll
    for (int i = 0; i < 6; i++) {
        float v = src[lane + i * 32];
        vals[i] = v; s += v; s2 += v * v;
    }
#pragma unroll
    for (int o = 16; o > 0; o >>= 1) {
        s  += __shfl_xor_sync(0xffffffffu, s,  o);
        s2 += __shfl_xor_sync(0xffffffffu, s2, o);
    }
    float m  = s * (1.0f / Cc);
    float rs = rsqrtf(s2 * (1.0f / Cc) - m * m + 1e-5f);
    __half* dst = T + (size_t)row * Cc;
#pragma unroll
    for (int i = 0; i < 6; i++) {
        int c = lane + i * 32;
        dst[c] = __float2half_rn((vals[i] - m) * rs * g[c] + be[c]);
    }
}

// ---------------- fp16 mma.sync GEMM, cp.async double-buffered --------------
// D[M,N] = A[M,K] @ B[K,N]  (A,B fp16 row-major; accum fp32)
// CTA tile 128x128, KT=64. 8 warps (4x2), warp tile 32x64, mma m16n8k16.
// SMEM per stage: A 128x64 halves (128B rows, XOR-swizzled 16B chunks),
//                 B  64x128 halves (256B rows, per-128B-half XOR swizzle).
// MODE 0: C(fp16) = D
// MODE 1: C(fp32) = D + bias + res_bchw
// MODE 2: C(fp16) = gelu(D + bias)
// MODE 3: out_bchw(fp32) = res_rowmaj(fp32) + D + bias
#define STG 32768   // bytes per stage (16K A + 16K B)

__device__ __forceinline__ void hmma(float* c, const uint32_t* a, const uint32_t* b) {
    asm volatile(
        "mma.sync.aligned.m16n8k16.row.col.f32.f16.f16.f32 "
        "{%0,%1,%2,%3}, {%4,%5,%6,%7}, {%8,%9}, {%0,%1,%2,%3};"
        : "+f"(c[0]), "+f"(c[1]), "+f"(c[2]), "+f"(c[3])
        : "r"(a[0]), "r"(a[1]), "r"(a[2]), "r"(a[3]), "r"(b[0]), "r"(b[1]));
}

template <int MODE>
__global__ __launch_bounds__(256, 1)
void hgemm(const __half* __restrict__ A, const __half* __restrict__ Bm,
           void* __restrict__ Cv, int M, int N, int K,
           const float* __restrict__ bias, const float* __restrict__ res) {
    extern __shared__ char smem[];
    uint32_t sb = smem_u32(smem);

    int tid  = threadIdx.x;
    int wid  = tid >> 5, lane = tid & 31;
    int wm   = wid & 3;
    int wn   = wid >> 2;
    int row0 = blockIdx.y * 128;
    int col0 = blockIdx.x * 128;
    int lg   = lane >> 2;
    int lt   = lane & 3;

    float cacc[2][8][4];
#pragma unroll
    for (int mt = 0; mt < 2; mt++)
#pragma unroll
        for (int nt = 0; nt < 8; nt++)
#pragma unroll
            for (int q = 0; q < 4; q++) cacc[mt][nt][q] = 0.f;

    int nk = K >> 6;  // K / 64

    // ---- stage loader (cp.async, 8 x 16B per thread) ----
    auto load_stage = [&](int kt, int buf) {
        uint32_t sA = sb + buf * STG;
        uint32_t sB = sA + 16384;
#pragma unroll
        for (int i = 0; i < 4; i++) {
            int idx = tid + i * 256;
            int m = idx >> 3, c = idx & 7;
            const __half* src = A + (size_t)(row0 + m) * K + (kt << 6) + (c << 3);
            uint32_t dst = sA + m * 128 + ((c ^ (m & 7)) << 4);
            asm volatile("cp.async.cg.shared.global [%0], [%1], 16;"
                         :: "r"(dst), "l"(src) : "memory");
        }
#pragma unroll
        for (int i = 0; i < 4; i++) {
            int idx = tid + i * 256;
            int k = idx >> 4, c = idx & 15;
            int n = col0 + (c << 3);
            const __half* src = Bm + (size_t)((kt << 6) + k) * N + (n < N ? n : 0);
            uint32_t dst = sB + k * 256 + (((c & 8) | ((c & 7) ^ (k & 7))) << 4);
            int ssz = (n < N) ? 16 : 0;
            asm volatile("cp.async.cg.shared.global [%0], [%1], 16, %2;"
                         :: "r"(dst), "l"(src), "r"(ssz) : "memory");
        }
    };

    load_stage(0, 0);
    asm volatile("cp.async.commit_group;" ::: "memory");

    for (int kt = 0; kt < nk; kt++) {
        int buf = kt & 1;
        if (kt + 1 < nk) {
            load_stage(kt + 1, buf ^ 1);
            asm volatile("cp.async.commit_group;" ::: "memory");
            asm volatile("cp.async.wait_group 1;" ::: "memory");
        } else {
            asm volatile("cp.async.wait_group 0;" ::: "memory");
        }
        __syncthreads();

        uint32_t sA = sb + buf * STG;
        uint32_t sB = sA + 16384;
#pragma unroll
        for (int ks = 0; ks < 4; ks++) {
            uint32_t af[2][4], bf[8][2];
#pragma unroll
            for (int mt = 0; mt < 2; mt++) {
                int m = wm * 32 + mt * 16 + (lane & 15);
                int c = ks * 2 + (lane >> 4);
                uint32_t addr = sA + m * 128 + ((c ^ (m & 7)) << 4);
                asm volatile("ldmatrix.sync.aligned.m8n8.x4.shared.b16 {%0,%1,%2,%3}, [%4];"
                             : "=r"(af[mt][0]), "=r"(af[mt][1]), "=r"(af[mt][2]), "=r"(af[mt][3])
                             : "r"(addr));
            }
#pragma unroll
            for (int np = 0; np < 4; np++) {
                int k  = ks * 16 + (lane & 15);
                int cn = wn * 8 + np * 2 + (lane >> 4);
                uint32_t addr = sB + k * 256 + (((cn & 8) | ((cn & 7) ^ (k & 7))) << 4);
                asm volatile("ldmatrix.sync.aligned.m8n8.x4.trans.shared.b16 {%0,%1,%2,%3}, [%4];"
                             : "=r"(bf[np * 2][0]), "=r"(bf[np * 2][1]),
                               "=r"(bf[np * 2 + 1][0]), "=r"(bf[np * 2 + 1][1])
                             : "r"(addr));
            }
#pragma unroll
            for (int mt = 0; mt < 2; mt++)
#pragma unroll
                for (int nt = 0; nt < 8; nt++)
                    hmma(cacc[mt][nt], af[mt], bf[nt]);
        }
        __syncthreads();
    }

    // ---------------- epilogue ----------------
#pragma unroll
    for (int mt = 0; mt < 2; mt++) {
#pragma unroll
        for (int nt = 0; nt < 8; nt++) {
            int r = row0 + wm * 32 + mt * 16 + lg;
            int c = col0 + wn * 64 + nt * 8 + lt * 2;
            if (c >= N) continue;
#pragma unroll
            for (int half = 0; half < 2; half++) {
                int rr = r + half * 8;
                float v0 = cacc[mt][nt][half * 2 + 0];
                float v1 = cacc[mt][nt][half * 2 + 1];
                int rb = rr >> 16, rhw = rr & (HW - 1);
                if (MODE == 0) {
                    *(__half2*)((__half*)Cv + (size_t)rr * N + c) = __floats2half2_rn(v0, v1);
                } else if (MODE == 1) {
                    const float* rp = res + (size_t)rb * Cc * HW + rhw;
                    float o0 = v0 + bias[c]     + rp[(size_t)c * HW];
                    float o1 = v1 + bias[c + 1] + rp[(size_t)(c + 1) * HW];
                    *(float2*)((float*)Cv + (size_t)rr * N + c) = make_float2(o0, o1);
                } else if (MODE == 2) {
                    *(__half2*)((__half*)Cv + (size_t)rr * N + c) =
                        __floats2half2_rn(gelu_exact(v0 + bias[c]),
                                          gelu_exact(v1 + bias[c + 1]));
                } else {
                    const float* rp = res + (size_t)rr * Cc;
                    float* op = (float*)Cv + (size_t)rb * Cc * HW + rhw;
                    op[(size_t)c * HW]       = rp[c]     + v0 + bias[c];
                    op[(size_t)(c + 1) * HW] = rp[c + 1] + v1 + bias[c + 1];
                }
            }
        }
    }
}

// ---------------- launch ----------------
extern "C" void kernel_launch(void* const* d_in, const int* in_sizes, int n_in,
                              void* d_out, int out_size) {
    const float* x       = (const float*)d_in[0];
    const float* norm1_g = (const float*)d_in[1];
    const float* norm1_b = (const float*)d_in[2];
    const float* w_sed   = (const float*)d_in[3];
    const float* proj_w  = (const float*)d_in[4];
    const float* proj_b  = (const float*)d_in[5];
    const float* norm2_g = (const float*)d_in[6];
    const float* norm2_b = (const float*)d_in[7];
    const float* fc1_w   = (const float*)d_in[8];
    const float* fc1_b   = (const float*)d_in[9];
    const float* fc2_w   = (const float*)d_in[10];
    const float* fc2_b   = (const float*)d_in[11];
    float* out = (float*)d_out;

    __half *wf, *Xw, *Y1, *Z, *T, *U, *projH, *fc1H, *fc2H;
    float *X2;
    cudaGetSymbolAddress((void**)&wf,    g_wf);
    cudaGetSymbolAddress((void**)&Xw,    g_Xw);
    cudaGetSymbolAddress((void**)&Y1,    g_Y1);
    cudaGetSymbolAddress((void**)&Z,     g_Z);
    cudaGetSymbolAddress((void**)&X2,    g_X2);
    cudaGetSymbolAddress((void**)&T,     g_T);
    cudaGetSymbolAddress((void**)&U,     g_U);
    cudaGetSymbolAddress((void**)&projH, g_projH);
    cudaGetSymbolAddress((void**)&fc1H,  g_fc1H);
    cudaGetSymbolAddress((void**)&fc2H,  g_fc2H);

    const int SMEM = 2 * STG;  // 65536
    cudaFuncSetAttribute(hgemm<0>, cudaFuncAttributeMaxDynamicSharedMemorySize, SMEM);
    cudaFuncSetAttribute(hgemm<1>, cudaFuncAttributeMaxDynamicSharedMemorySize, SMEM);
    cudaFuncSetAttribute(hgemm<2>, cudaFuncAttributeMaxDynamicSharedMemorySize, SMEM);
    cudaFuncSetAttribute(hgemm<3>, cudaFuncAttributeMaxDynamicSharedMemorySize, SMEM);

    // 0. structured weight + fp16 conversions
    build_wf_kernel<<<(DWIN * (DWIN / 4) + 255) / 256, 256>>>(w_sed, wf);
    convert_h_kernel<<<(Cc * Cc + 255) / 256, 256>>>(proj_w, projH, Cc * Cc);
    convert_h_kernel<<<(Cc * DH + 255) / 256, 256>>>(fc1_w, fc1H, Cc * DH);
    convert_h_kernel<<<(DH * Cc + 255) / 256, 256>>>(fc2_w, fc2H, DH * Cc);

    // 1. LN1 + window partition (fp16)
    ln1_window_kernel<<<(NPIX + 255) / 256, 256>>>(x, norm1_g, norm1_b, Xw);

    // 2. Sedenion GEMM: Y1 = Xw @ wf   (8192 x 3072 x 3072)
    hgemm<0><<<dim3(DWIN / 128, NWIN / 128), 256, SMEM>>>(
        Xw, wf, Y1, NWIN, DWIN, DWIN, nullptr, nullptr);

    // 3. reverse window + GELU -> Z (fp16)
    gather_gelu_kernel<<<(NPIX * (Cc / 4) + 255) / 256, 256>>>(Y1, Z);

    // 4. proj + bias + residual(x) -> X2 fp32   (131072 x 192 x 192)
    hgemm<1><<<dim3(2, NPIX / 128), 256, SMEM>>>(
        Z, projH, X2, NPIX, Cc, Cc, proj_b, x);

    // 5. LN2 -> T (fp16)
    ln2_kernel<<<(NPIX * 32 + 255) / 256, 256>>>(X2, norm2_g, norm2_b, T);

    // 6. fc1 + bias + GELU -> U fp16   (131072 x 768 x 192)
    hgemm<2><<<dim3(DH / 128, NPIX / 128), 256, SMEM>>>(
        T, fc1H, U, NPIX, DH, Cc, fc1_b, nullptr);

    // 7. fc2 + bias + residual(X2), transposed store -> out fp32
    hgemm<3><<<dim3(2, NPIX / 128), 256, SMEM>>>(
        U, fc2H, out, NPIX, Cc, DH, fc2_b, X2);
}

// round 5
// speedup vs baseline: 5.8306x; 1.3123x over previous
#include <cuda_runtime.h>
#include <cuda_fp16.h>
#include <cstdint>
#include <math.h>

// ---------------- problem constants ----------------
#define Cc   192
#define HW   65536           // 256*256
#define NPIX 131072          // B*H*W
#define DWIN 3072            // 16*C
#define NWIN 8192            // B*(H/4)*(W/4)
#define DH   768             // 4*C

// ---------------- scratch (device globals: allocation-free) ----------------
__device__ __half g_wf [(size_t)DWIN * DWIN];      // 18.9 MB  ([K][N] row-major)
__device__ __half g_Xw [(size_t)NWIN * DWIN];      // 50.3 MB
__device__ __half g_Z  [(size_t)NPIX * Cc];        // 50.3 MB
__device__ float  g_X2 [(size_t)NPIX * Cc];        // 100.7 MB (residual chain: fp32)
__device__ __half g_T  [(size_t)NPIX * Cc];        // 50.3 MB
__device__ __half g_U  [(size_t)NPIX * DH];        // 201.3 MB
__device__ __half g_projH[Cc * Cc];
__device__ __half g_fc1H [Cc * DH];
__device__ __half g_fc2H [DH * Cc];

// ---------------- helpers ----------------
__device__ __forceinline__ float gelu_exact(float x) {
    return 0.5f * x * (1.0f + erff(x * 0.70710678118654752f));
}
__device__ __forceinline__ uint32_t smem_u32(const void* p) {
    uint32_t a;
    asm("{ .reg .u64 t; cvta.to.shared.u64 t, %1; cvt.u32.u64 %0, t; }" : "=r"(a) : "l"(p));
    return a;
}

__device__ __forceinline__ int cd_sign16(int i, int j) {
    int s = 1;
    for (int n = 16; n > 1;) {
        int h = n >> 1;
        if (i < h && j < h) {
        } else if (i < h) {
            int t = j - h; j = i; i = t;
        } else if (j < h) {
            if (j != 0) s = -s;
            i = i - h;
        } else {
            int ip = i - h, jp = j - h;
            if (jp == 0) s = -s;
            i = jp; j = ip;
        }
        n = h;
    }
    return s;
}

// ---------------- kernel: build wf (3072 x 3072, [K][N], fp16) -------------
__global__ void build_wf_kernel(const float* __restrict__ w_sed, __half* __restrict__ wf) {
    int e4 = blockIdx.x * blockDim.x + threadIdx.x;
    if (e4 >= DWIN * (DWIN / 4)) return;
    int row  = e4 / (DWIN / 4);
    int col4 = (e4 % (DWIN / 4)) * 4;
    int i = row / Cc, a = row % Cc;
    int k = col4 / Cc, b = col4 % Cc;
    int j = i ^ k;
    float s = (float)cd_sign16(i, j);
    float4 v = *(const float4*)(w_sed + ((size_t)j * Cc + a) * Cc + b);
    __half2* d = (__half2*)(wf + (size_t)row * DWIN + col4);
    d[0] = __floats2half2_rn(s * v.x, s * v.y);
    d[1] = __floats2half2_rn(s * v.z, s * v.w);
}

// ---------------- kernel: fp32 -> fp16 weight convert ----------------------
__global__ void convert_h_kernel(const float* __restrict__ w, __half* __restrict__ wh, int n) {
    int o = blockIdx.x * blockDim.x + threadIdx.x;
    if (o < n) wh[o] = __float2half_rn(w[o]);
}

// ---------------- kernel: LN1 over channels + window scatter (fp16 out) ----
__global__ void ln1_window_kernel(const float* __restrict__ x,
                                  const float* __restrict__ g,
                                  const float* __restrict__ be,
                                  __half* __restrict__ Xw) {
    int n = blockIdx.x * blockDim.x + threadIdx.x;
    if (n >= NPIX) return;
    int b = n >> 16, hw = n & (HW - 1);
    int h = hw >> 8, w = hw & 255;
    const float* px = x + (size_t)b * Cc * HW + hw;
    float s = 0.f, s2 = 0.f;
#pragma unroll 4
    for (int c = 0; c < Cc; c++) {
        float v = px[(size_t)c * HW];
        s += v; s2 += v * v;
    }
    float m  = s * (1.0f / Cc);
    float rs = rsqrtf(s2 * (1.0f / Cc) - m * m + 1e-5f);
    int r = (b << 12) + ((h >> 2) << 6) + (w >> 2);
    int p = ((h & 3) << 2) + (w & 3);
    __half* dst = Xw + (size_t)r * DWIN + p * Cc;
#pragma unroll 4
    for (int c = 0; c < Cc; c++) {
        float v = px[(size_t)c * HW];
        dst[c] = __float2half_rn((v - m) * rs * g[c] + be[c]);
    }
}

// ---------------- kernel: LN2, one warp per row (fp32 in, fp16 out) --------
__global__ void ln2_kernel(const float* __restrict__ X2,
                           const float* __restrict__ g,
                           const float* __restrict__ be,
                           __half* __restrict__ T) {
    int gt   = blockIdx.x * blockDim.x + threadIdx.x;
    int row  = gt >> 5;
    int lane = gt & 31;
    if (row >= NPIX) return;
    const float* src = X2 + (size_t)row * Cc;
    float vals[6];
    float s = 0.f, s2 = 0.f;
#pragma unroll
    for (int i = 0; i < 6; i++) {
        float v = src[lane + i * 32];
        vals[i] = v; s += v; s2 += v * v;
    }
#pragma unroll
    for (int o = 16; o > 0; o >>= 1) {
        s  += __shfl_xor_sync(0xffffffffu, s,  o);
        s2 += __shfl_xor_sync(0xffffffffu, s2, o);
    }
    float m  = s * (1.0f / Cc);
    float rs = rsqrtf(s2 * (1.0f / Cc) - m * m + 1e-5f);
    __half* dst = T + (size_t)row * Cc;
#pragma unroll
    for (int i = 0; i < 6; i++) {
        int c = lane + i * 32;
        dst[c] = __float2half_rn((vals[i] - m) * rs * g[c] + be[c]);
    }
}

// ---------------- fp16 mma.sync GEMM, 3-stage cp.async pipeline -------------
// D[M,N] = A[M,K] @ B[K,N]  (A,B fp16 row-major; accum fp32)
// CTA tile 128x128, KT=64, 3 smem stages, 1 syncthreads per k-tile, 2 CTAs/SM.
// MODE 1: C(fp32) = D + bias + res_bchw
// MODE 2: C(fp16) = gelu(D + bias)
// MODE 3: out_bchw(fp32) = res_rowmaj(fp32) + D + bias
// MODE 4: Z(fp16) = gelu(D), reverse-window scatter (fused GEMM1 epilogue)
#define STG 32768   // bytes per stage (16K A + 16K B)

__device__ __forceinline__ void hmma(float* c, const uint32_t* a, const uint32_t* b) {
    asm volatile(
        "mma.sync.aligned.m16n8k16.row.col.f32.f16.f16.f32 "
        "{%0,%1,%2,%3}, {%4,%5,%6,%7}, {%8,%9}, {%0,%1,%2,%3};"
        : "+f"(c[0]), "+f"(c[1]), "+f"(c[2]), "+f"(c[3])
        : "r"(a[0]), "r"(a[1]), "r"(a[2]), "r"(a[3]), "r"(b[0]), "r"(b[1]));
}

template <int MODE>
__global__ __launch_bounds__(256, 2)
void hgemm(const __half* __restrict__ A, const __half* __restrict__ Bm,
           void* __restrict__ Cv, int M, int N, int K,
           const float* __restrict__ bias, const float* __restrict__ res) {
    extern __shared__ char smem[];
    uint32_t sb = smem_u32(smem);

    int tid  = threadIdx.x;
    int wid  = tid >> 5, lane = tid & 31;
    int wm   = wid & 3;
    int wn   = wid >> 2;
    int row0 = blockIdx.y * 128;
    int col0 = blockIdx.x * 128;
    int lg   = lane >> 2;
    int lt   = lane & 3;

    float cacc[2][8][4];
#pragma unroll
    for (int mt = 0; mt < 2; mt++)
#pragma unroll
        for (int nt = 0; nt < 8; nt++)
#pragma unroll
            for (int q = 0; q < 4; q++) cacc[mt][nt][q] = 0.f;

    int nk = K >> 6;  // K / 64

    auto load_stage = [&](int kt, int buf) {
        uint32_t sA = sb + buf * STG;
        uint32_t sB = sA + 16384;
#pragma unroll
        for (int i = 0; i < 4; i++) {
            int idx = tid + i * 256;
            int m = idx >> 3, c = idx & 7;
            const __half* src = A + (size_t)(row0 + m) * K + (kt << 6) + (c << 3);
            uint32_t dst = sA + m * 128 + ((c ^ (m & 7)) << 4);
            asm volatile("cp.async.cg.shared.global [%0], [%1], 16;"
                         :: "r"(dst), "l"(src) : "memory");
        }
#pragma unroll
        for (int i = 0; i < 4; i++) {
            int idx = tid + i * 256;
            int k = idx >> 4, c = idx & 15;
            int n = col0 + (c << 3);
            const __half* src = Bm + (size_t)((kt << 6) + k) * N + (n < N ? n : 0);
            uint32_t dst = sB + k * 256 + (((c & 8) | ((c & 7) ^ (k & 7))) << 4);
            int ssz = (n < N) ? 16 : 0;
            asm volatile("cp.async.cg.shared.global [%0], [%1], 16, %2;"
                         :: "r"(dst), "l"(src), "r"(ssz) : "memory");
        }
        asm volatile("cp.async.commit_group;" ::: "memory");
    };

    // prologue: stages 0 and 1 in flight
    load_stage(0, 0);
    if (nk > 1) load_stage(1, 1);

    for (int kt = 0; kt < nk; kt++) {
        int buf = kt % 3;
        if (kt + 1 < nk) {
            asm volatile("cp.async.wait_group 1;" ::: "memory");
        } else {
            asm volatile("cp.async.wait_group 0;" ::: "memory");
        }
        __syncthreads();
        if (kt + 2 < nk) load_stage(kt + 2, (kt + 2) % 3);

        uint32_t sA = sb + buf * STG;
        uint32_t sB = sA + 16384;
#pragma unroll
        for (int ks = 0; ks < 4; ks++) {
            uint32_t af[2][4], bf[8][2];
#pragma unroll
            for (int mt = 0; mt < 2; mt++) {
                int m = wm * 32 + mt * 16 + (lane & 15);
                int c = ks * 2 + (lane >> 4);
                uint32_t addr = sA + m * 128 + ((c ^ (m & 7)) << 4);
                asm volatile("ldmatrix.sync.aligned.m8n8.x4.shared.b16 {%0,%1,%2,%3}, [%4];"
                             : "=r"(af[mt][0]), "=r"(af[mt][1]), "=r"(af[mt][2]), "=r"(af[mt][3])
                             : "r"(addr));
            }
#pragma unroll
            for (int np = 0; np < 4; np++) {
                int k  = ks * 16 + (lane & 15);
                int cn = wn * 8 + np * 2 + (lane >> 4);
                uint32_t addr = sB + k * 256 + (((cn & 8) | ((cn & 7) ^ (k & 7))) << 4);
                asm volatile("ldmatrix.sync.aligned.m8n8.x4.trans.shared.b16 {%0,%1,%2,%3}, [%4];"
                             : "=r"(bf[np * 2][0]), "=r"(bf[np * 2][1]),
                               "=r"(bf[np * 2 + 1][0]), "=r"(bf[np * 2 + 1][1])
                             : "r"(addr));
            }
#pragma unroll
            for (int mt = 0; mt < 2; mt++)
#pragma unroll
                for (int nt = 0; nt < 8; nt++)
                    hmma(cacc[mt][nt], af[mt], bf[nt]);
        }
    }
    __syncthreads();

    // ---------------- epilogue ----------------
#pragma unroll
    for (int mt = 0; mt < 2; mt++) {
#pragma unroll
        for (int nt = 0; nt < 8; nt++) {
            int r = row0 + wm * 32 + mt * 16 + lg;
            int c = col0 + wn * 64 + nt * 8 + lt * 2;
            if (c >= N) continue;
#pragma unroll
            for (int half = 0; half < 2; half++) {
                int rr = r + half * 8;
                float v0 = cacc[mt][nt][half * 2 + 0];
                float v1 = cacc[mt][nt][half * 2 + 1];
                if (MODE == 1) {
                    int rb = rr >> 16, rhw = rr & (HW - 1);
                    const float* rp = res + (size_t)rb * Cc * HW + rhw;
                    float o0 = v0 + bias[c]     + rp[(size_t)c * HW];
                    float o1 = v1 + bias[c + 1] + rp[(size_t)(c + 1) * HW];
                    *(float2*)((float*)Cv + (size_t)rr * N + c) = make_float2(o0, o1);
                } else if (MODE == 2) {
                    *(__half2*)((__half*)Cv + (size_t)rr * N + c) =
                        __floats2half2_rn(gelu_exact(v0 + bias[c]),
                                          gelu_exact(v1 + bias[c + 1]));
                } else if (MODE == 3) {
                    int rb = rr >> 16, rhw = rr & (HW - 1);
                    const float* rp = res + (size_t)rr * Cc;
                    float* op = (float*)Cv + (size_t)rb * Cc * HW + rhw;
                    op[(size_t)c * HW]       = rp[c]     + v0 + bias[c];
                    op[(size_t)(c + 1) * HW] = rp[c + 1] + v1 + bias[c + 1];
                } else {  // MODE 4: gelu + reverse-window scatter to Z (fp16)
                    int p  = c / Cc;
                    int cc = c - p * Cc;
                    int bb = rr >> 12;
                    int hq = (rr >> 6) & 63, wq = rr & 63;
                    int h = (hq << 2) + (p >> 2), w = (wq << 2) + (p & 3);
                    int n = (bb << 16) + (h << 8) + w;
                    *(__half2*)((__half*)Cv + (size_t)n * Cc + cc) =
                        __floats2half2_rn(gelu_exact(v0), gelu_exact(v1));
                }
            }
        }
    }
}

// ---------------- launch ----------------
extern "C" void kernel_launch(void* const* d_in, const int* in_sizes, int n_in,
                              void* d_out, int out_size) {
    const float* x       = (const float*)d_in[0];
    const float* norm1_g = (const float*)d_in[1];
    const float* norm1_b = (const float*)d_in[2];
    const float* w_sed   = (const float*)d_in[3];
    const float* proj_w  = (const float*)d_in[4];
    const float* proj_b  = (const float*)d_in[5];
    const float* norm2_g = (const float*)d_in[6];
    const float* norm2_b = (const float*)d_in[7];
    const float* fc1_w   = (const float*)d_in[8];
    const float* fc1_b   = (const float*)d_in[9];
    const float* fc2_w   = (const float*)d_in[10];
    const float* fc2_b   = (const float*)d_in[11];
    float* out = (float*)d_out;

    __half *wf, *Xw, *Z, *T, *U, *projH, *fc1H, *fc2H;
    float *X2;
    cudaGetSymbolAddress((void**)&wf,    g_wf);
    cudaGetSymbolAddress((void**)&Xw,    g_Xw);
    cudaGetSymbolAddress((void**)&Z,     g_Z);
    cudaGetSymbolAddress((void**)&X2,    g_X2);
    cudaGetSymbolAddress((void**)&T,     g_T);
    cudaGetSymbolAddress((void**)&U,     g_U);
    cudaGetSymbolAddress((void**)&projH, g_projH);
    cudaGetSymbolAddress((void**)&fc1H,  g_fc1H);
    cudaGetSymbolAddress((void**)&fc2H,  g_fc2H);

    const int SMEM = 3 * STG;  // 98304
    cudaFuncSetAttribute(hgemm<1>, cudaFuncAttributeMaxDynamicSharedMemorySize, SMEM);
    cudaFuncSetAttribute(hgemm<2>, cudaFuncAttributeMaxDynamicSharedMemorySize, SMEM);
    cudaFuncSetAttribute(hgemm<3>, cudaFuncAttributeMaxDynamicSharedMemorySize, SMEM);
    cudaFuncSetAttribute(hgemm<4>, cudaFuncAttributeMaxDynamicSharedMemorySize, SMEM);

    // 0. structured weight + fp16 conversions
    build_wf_kernel<<<(DWIN * (DWIN / 4) + 255) / 256, 256>>>(w_sed, wf);
    convert_h_kernel<<<(Cc * Cc + 255) / 256, 256>>>(proj_w, projH, Cc * Cc);
    convert_h_kernel<<<(Cc * DH + 255) / 256, 256>>>(fc1_w, fc1H, Cc * DH);
    convert_h_kernel<<<(DH * Cc + 255) / 256, 256>>>(fc2_w, fc2H, DH * Cc);

    // 1. LN1 + window partition (fp16)
    ln1_window_kernel<<<(NPIX + 255) / 256, 256>>>(x, norm1_g, norm1_b, Xw);

    // 2. Sedenion GEMM + GELU + reverse-window scatter -> Z (fused epilogue)
    hgemm<4><<<dim3(DWIN / 128, NWIN / 128), 256, SMEM>>>(
        Xw, wf, Z, NWIN, DWIN, DWIN, nullptr, nullptr);

    // 3. proj + bias + residual(x) -> X2 fp32   (131072 x 192 x 192)
    hgemm<1><<<dim3(2, NPIX / 128), 256, SMEM>>>(
        Z, projH, X2, NPIX, Cc, Cc, proj_b, x);

    // 4. LN2 -> T (fp16)
    ln2_kernel<<<(NPIX * 32 + 255) / 256, 256>>>(X2, norm2_g, norm2_b, T);

    // 5. fc1 + bias + GELU -> U fp16   (131072 x 768 x 192)
    hgemm<2><<<dim3(DH / 128, NPIX / 128), 256, SMEM>>>(
        T, fc1H, U, NPIX, DH, Cc, fc1_b, nullptr);

    // 6. fc2 + bias + residual(X2), transposed store -> out fp32
    hgemm<3><<<dim3(2, NPIX / 128), 256, SMEM>>>(
        U, fc2H, out, NPIX, Cc, DH, fc2_b, X2);
}